// round 15
// baseline (speedup 1.0000x reference)
#include <cuda_runtime.h>
#include <math.h>

#define N_NODES   8192
#define K_NBR     64
#define TWO_N     (2 * N_NODES)
#define BN_EPS    1e-3f

// Single fused kernel: 64 builders + 512 GEMV blocks = 576 blocks, all
// co-resident (148 SMs x 4 blocks at 256 threads) -> all spins deadlock-free.
// Chunk c covers rows [128c,+128) u [N+128c,+128): blocks stream their
// dependency-free lower half first (builder flag long set by phase B).
// Tail: every GEMV block reduces its own 16 output columns from L2-hot
// partials (W streamed with __ldcs so partials are never evicted).
#define N_BUILDERS     64
#define NODES_PER_B    (N_NODES / N_BUILDERS)   // 128
#define COL_TILES      8
#define ROW_CHUNKS     64
#define HALF_ROWS      128
#define THREADS_B      256
#define GRID_TOTAL     (N_BUILDERS + COL_TILES * ROW_CHUNKS)

// scratch (no allocation allowed). Zero-initialized at load; flags/counters
// self-reset every execution -> graph-replay safe.
__device__ float g_h[TWO_N];                     // only rows >= N used
__device__ float g_part[ROW_CHUNKS * N_NODES];
__device__ int   g_flag[N_BUILDERS];
__device__ int   g_cnt[N_BUILDERS];
__device__ int   g_done[COL_TILES];              // GEMV completions per tile
__device__ int   g_rdone[COL_TILES];             // reducer completions per tile

__device__ __forceinline__ float gelu_erf(float z) {
    return 0.5f * z * (1.0f + erff(z * 0.70710678118654752440f));
}

// ---------------------------------------------------------------------------
__global__ __launch_bounds__(THREADS_B)
void fused_kernel(const float* __restrict__ x,
                  const int* __restrict__ adj,
                  const float* __restrict__ W,
                  const float* __restrict__ gamma,
                  const float* __restrict__ beta,
                  const float* __restrict__ mean,
                  const float* __restrict__ var,
                  const float* __restrict__ bias,
                  float* __restrict__ out)
{
    __shared__ float sh[2 * HALF_ROWS];
    const int tid = threadIdx.x;

    if (blockIdx.x < N_BUILDERS) {
        // ================= builder b: BN(x + ngh_sum) for nodes [128b,+128)
        const int b        = blockIdx.x;
        const int warpId   = tid >> 5;
        const int lane     = tid & 31;
        const int nodeBase = b * NODES_PER_B + warpId * 16;   // 16 nodes/warp
        const int2* adj2   = reinterpret_cast<const int2*>(adj);

        #pragma unroll
        for (int g = 0; g < 16; g += 8) {
            int2 a[8];
            #pragma unroll
            for (int i = 0; i < 8; ++i)
                a[i] = __ldg(&adj2[(nodeBase + g + i) * 32 + lane]);

            float s[8];
            #pragma unroll
            for (int i = 0; i < 8; ++i)
                s[i] = __ldg(&x[a[i].x]) + __ldg(&x[a[i].y]);

            #pragma unroll
            for (int off = 16; off > 0; off >>= 1) {
                #pragma unroll
                for (int i = 0; i < 8; ++i)
                    s[i] += __shfl_down_sync(0xffffffffu, s[i], off);
            }

            if (lane == 0) {
                #pragma unroll
                for (int i = 0; i < 8; ++i) {
                    const int node = nodeBase + g + i;
                    const int j    = N_NODES + node;
                    float agg = __ldg(&x[node]) + s[i];
                    float inv = rsqrtf(var[j] + BN_EPS);
                    g_h[j] = (agg - mean[j]) * inv * gamma[j] + beta[j];
                }
            }
        }

        __threadfence();
        __syncthreads();
        if (tid == 0)
            atomicExch(&g_flag[b], 1);   // release
        return;
    }

    // ================= GEMV block ==========================================
    const int gid     = blockIdx.x - N_BUILDERS;
    const int colTile = gid & (COL_TILES - 1);
    const int chunk   = gid >> 3;                 // 0..63
    const int colBase = colTile * (THREADS_B * 4) + tid * 4;
    const int rowA    = chunk * HALF_ROWS;        // lower-half base (< N)
    const int rowB    = N_NODES + rowA;           // upper-half base (>= N)

    // ---- phase A: dependency-free lower rows, stream starts immediately --
    if (tid < HALF_ROWS) {
        const int row = rowA + tid;
        float v   = x[row];
        float inv = rsqrtf(var[row] + BN_EPS);
        sh[tid] = (v - mean[row]) * inv * gamma[row] + beta[row];
    }
    __syncthreads();

    float4 acc = make_float4(0.f, 0.f, 0.f, 0.f);
    {
        const float4* wp = reinterpret_cast<const float4*>(
            W + (long long)rowA * N_NODES + colBase);
        const int strideV = N_NODES / 4;
        #pragma unroll 8
        for (int r = 0; r < HALF_ROWS; ++r) {
            float  hv = sh[r];
            float4 w  = __ldcs(wp);       // evict-first: W is read-once
            acc.x = fmaf(hv, w.x, acc.x);
            acc.y = fmaf(hv, w.y, acc.y);
            acc.z = fmaf(hv, w.z, acc.z);
            acc.w = fmaf(hv, w.w, acc.w);
            wp += strideV;
        }
    }

    // ---- phase B: upper rows; builder long done -> first poll passes -----
    if (tid == 0) {
        while (atomicAdd(&g_flag[chunk], 0) == 0) __nanosleep(64);
        __threadfence();   // acquire
    }
    __syncthreads();
    if (tid < HALF_ROWS)
        sh[HALF_ROWS + tid] = __ldcg(&g_h[rowB + tid]);
    __syncthreads();
    // self-resetting consumption (8 consumer blocks per flag)
    if (tid == 0) {
        if (atomicAdd(&g_cnt[chunk], 1) == COL_TILES - 1) {
            atomicExch(&g_cnt[chunk], 0);
            atomicExch(&g_flag[chunk], 0);
        }
    }

    {
        const float4* wp = reinterpret_cast<const float4*>(
            W + (long long)rowB * N_NODES + colBase);
        const int strideV = N_NODES / 4;
        #pragma unroll 8
        for (int r = 0; r < HALF_ROWS; ++r) {
            float  hv = sh[HALF_ROWS + r];
            float4 w  = __ldcs(wp);       // evict-first: W is read-once
            acc.x = fmaf(hv, w.x, acc.x);
            acc.y = fmaf(hv, w.y, acc.y);
            acc.z = fmaf(hv, w.z, acc.z);
            acc.w = fmaf(hv, w.w, acc.w);
            wp += strideV;
        }
    }

    *reinterpret_cast<float4*>(&g_part[chunk * N_NODES + colBase]) = acc;

    // ---- tail: every block reduces its own 16 columns --------------------
    __threadfence();          // partial visible before counter bump (release)
    __syncthreads();
    if (tid == 0) {
        atomicAdd(&g_done[colTile], 1);
        while (atomicAdd(&g_done[colTile], 0) < ROW_CHUNKS) __nanosleep(128);
        __threadfence();      // acquire: all 64 partials of this tile visible
    }
    __syncthreads();

    // cols [myCol0, +16); thread t: column myCol0 + (t&15), chunk-group t>>4
    const int myCol0 = colTile * 1024 + chunk * 16;
    const int cLoc   = tid & 15;
    const int grp    = tid >> 4;                  // 0..15, 4 chunks each
    float s = 0.f;
    #pragma unroll
    for (int c = grp * 4; c < grp * 4 + 4; ++c)
        s += __ldcg(&g_part[c * N_NODES + myCol0 + cLoc]);   // L2-hot

    sh[tid] = s;              // reuse sh (all prior reads done)
    __syncthreads();

    if (tid < 16) {
        float t = 0.f;
        #pragma unroll
        for (int k = 0; k < 16; ++k)
            t += sh[k * 16 + tid];
        const int col = myCol0 + tid;
        out[col] = gelu_erf(t + bias[col]);
    }

    // self-reset: 64th reducer of the tile clears both counters
    __syncthreads();
    if (tid == 0) {
        if (atomicAdd(&g_rdone[colTile], 1) == ROW_CHUNKS - 1) {
            atomicExch(&g_rdone[colTile], 0);
            atomicExch(&g_done[colTile], 0);
        }
    }
}

// ---------------------------------------------------------------------------
extern "C" void kernel_launch(void* const* d_in, const int* in_sizes, int n_in,
                              void* d_out, int out_size)
{
    const float* x     = (const float*)d_in[0];  // input_data [1,N]
    const int*   adj   = (const int*)d_in[1];    // adj [N,K] int32 (JAX x64 off)
    // d_in[2] = edge_weights (unused by reference)
    const float* W     = (const float*)d_in[3];  // [2N, N]
    const float* b     = (const float*)d_in[4];  // [N]
    const float* gamma = (const float*)d_in[5];  // [2N]
    const float* beta  = (const float*)d_in[6];  // [2N]
    const float* mean  = (const float*)d_in[7];  // [2N]
    const float* var   = (const float*)d_in[8];  // [2N]
    float*       out   = (float*)d_out;

    fused_kernel<<<GRID_TOTAL, THREADS_B>>>(x, adj, W, gamma, beta, mean, var,
                                            b, out);
}

// round 16
// speedup vs baseline: 1.0111x; 1.0111x over previous
#include <cuda_runtime.h>
#include <math.h>

#define N_NODES   8192
#define K_NBR     64
#define TWO_N     (2 * N_NODES)
#define BN_EPS    1e-3f

// Fused kernel: 64 builders + 512 GEMV blocks = 576 blocks, all co-resident
// (148 SMs x 4 blocks at 256 threads) -> spin is deadlock-free.
// Chunk c covers rows [128c,128c+128) u [N+128c, N+128c+128): each GEMV
// block streams its dependency-free lower half FIRST (~35us of W), so the
// builder flag is long set when the upper half starts -> zero wait.
#define N_BUILDERS     64
#define NODES_PER_B    (N_NODES / N_BUILDERS)   // 128
#define COL_TILES      8
#define ROW_CHUNKS     64
#define HALF_ROWS      128                       // rows per phase
#define THREADS_B      256
#define GRID_TOTAL     (N_BUILDERS + COL_TILES * ROW_CHUNKS)

// scratch (no allocation allowed). Zero-initialized at load; flags/counters
// self-reset every execution -> graph-replay safe.
__device__ float g_h[TWO_N];                     // only rows >= N used
__device__ float g_part[ROW_CHUNKS * N_NODES];
__device__ int   g_flag[N_BUILDERS];
__device__ int   g_cnt[N_BUILDERS];

__device__ __forceinline__ float gelu_erf(float z) {
    return 0.5f * z * (1.0f + erff(z * 0.70710678118654752440f));
}

// ---------------------------------------------------------------------------
__global__ __launch_bounds__(THREADS_B)
void fused_kernel(const float* __restrict__ x,
                  const int* __restrict__ adj,
                  const float* __restrict__ W,
                  const float* __restrict__ gamma,
                  const float* __restrict__ beta,
                  const float* __restrict__ mean,
                  const float* __restrict__ var)
{
    __shared__ float sh[2 * HALF_ROWS];
    const int tid = threadIdx.x;

    if (blockIdx.x < N_BUILDERS) {
        // ================= builder b: BN(x + ngh_sum) for nodes [128b,+128)
        const int b        = blockIdx.x;
        const int warpId   = tid >> 5;
        const int lane     = tid & 31;
        const int nodeBase = b * NODES_PER_B + warpId * 16;   // 16 nodes/warp
        const int2* adj2   = reinterpret_cast<const int2*>(adj);

        #pragma unroll
        for (int g = 0; g < 16; g += 8) {
            int2 a[8];
            #pragma unroll
            for (int i = 0; i < 8; ++i)
                a[i] = __ldg(&adj2[(nodeBase + g + i) * 32 + lane]);

            float s[8];
            #pragma unroll
            for (int i = 0; i < 8; ++i)
                s[i] = __ldg(&x[a[i].x]) + __ldg(&x[a[i].y]);

            #pragma unroll
            for (int off = 16; off > 0; off >>= 1) {
                #pragma unroll
                for (int i = 0; i < 8; ++i)
                    s[i] += __shfl_down_sync(0xffffffffu, s[i], off);
            }

            if (lane == 0) {
                #pragma unroll
                for (int i = 0; i < 8; ++i) {
                    const int node = nodeBase + g + i;
                    const int j    = N_NODES + node;
                    float agg = __ldg(&x[node]) + s[i];
                    float inv = rsqrtf(var[j] + BN_EPS);
                    g_h[j] = (agg - mean[j]) * inv * gamma[j] + beta[j];
                }
            }
        }

        __threadfence();
        __syncthreads();
        if (tid == 0)
            atomicExch(&g_flag[b], 1);   // release
        cudaTriggerProgrammaticLaunchCompletion();
        return;
    }

    // ================= GEMV block ==========================================
    const int gid     = blockIdx.x - N_BUILDERS;
    const int colTile = gid & (COL_TILES - 1);
    const int chunk   = gid >> 3;                 // 0..63
    const int colBase = colTile * (THREADS_B * 4) + tid * 4;
    const int rowA    = chunk * HALF_ROWS;        // lower-half base (< N)
    const int rowB    = N_NODES + rowA;           // upper-half base (>= N)

    // ---- phase A: dependency-free lower rows, stream starts immediately --
    if (tid < HALF_ROWS) {
        const int row = rowA + tid;
        float v   = x[row];
        float inv = rsqrtf(var[row] + BN_EPS);
        sh[tid] = (v - mean[row]) * inv * gamma[row] + beta[row];
    }
    __syncthreads();

    float4 acc = make_float4(0.f, 0.f, 0.f, 0.f);
    {
        const float4* wp = reinterpret_cast<const float4*>(
            W + (long long)rowA * N_NODES + colBase);
        const int strideV = N_NODES / 4;
        #pragma unroll 8
        for (int r = 0; r < HALF_ROWS; ++r) {
            float  hv = sh[r];
            float4 w  = __ldcs(wp);       // evict-first: W is read-once
            acc.x = fmaf(hv, w.x, acc.x);
            acc.y = fmaf(hv, w.y, acc.y);
            acc.z = fmaf(hv, w.z, acc.z);
            acc.w = fmaf(hv, w.w, acc.w);
            wp += strideV;
        }
    }

    // ---- phase B: upper rows; builder long done -> first poll passes -----
    if (tid == 0) {
        while (atomicAdd(&g_flag[chunk], 0) == 0) __nanosleep(64);
        __threadfence();   // acquire
    }
    __syncthreads();
    if (tid < HALF_ROWS)
        sh[HALF_ROWS + tid] = __ldcg(&g_h[rowB + tid]);
    __syncthreads();
    // self-resetting consumption (8 consumer blocks per flag)
    if (tid == 0) {
        if (atomicAdd(&g_cnt[chunk], 1) == COL_TILES - 1) {
            atomicExch(&g_cnt[chunk], 0);
            atomicExch(&g_flag[chunk], 0);
        }
    }

    {
        const float4* wp = reinterpret_cast<const float4*>(
            W + (long long)rowB * N_NODES + colBase);
        const int strideV = N_NODES / 4;
        #pragma unroll 8
        for (int r = 0; r < HALF_ROWS; ++r) {
            float  hv = sh[HALF_ROWS + r];
            float4 w  = __ldcs(wp);       // evict-first: W is read-once
            acc.x = fmaf(hv, w.x, acc.x);
            acc.y = fmaf(hv, w.y, acc.y);
            acc.z = fmaf(hv, w.z, acc.z);
            acc.w = fmaf(hv, w.w, acc.w);
            wp += strideV;
        }
    }

    *reinterpret_cast<float4*>(&g_part[chunk * N_NODES + colBase]) = acc;

    // release partials to the PDL-dependent kernel as early as possible
    __threadfence();
    cudaTriggerProgrammaticLaunchCompletion();
}

// ---------------------------------------------------------------------------
// K3: two-level parallel reduce + bias + exact-erf gelu.
// Launched with PDL: blocks start while fused_kernel drains; the
// grid-dependency sync releases once all fused blocks trigger. With W
// loaded via __ldcs, the 2MB of partials stay L2-resident -> fast reads.
// ---------------------------------------------------------------------------
__global__ __launch_bounds__(1024)
void reduce_gelu_kernel(const float* __restrict__ bias,
                        float* __restrict__ out)
{
    cudaGridDependencySynchronize();   // PDL: wait for fused_kernel triggers

    __shared__ float red[4][256];

    const int jLocal = threadIdx.x & 255;
    const int cg     = threadIdx.x >> 8;          // 0..3
    const int j      = blockIdx.x * 256 + jLocal;

    float s = 0.f;
    #pragma unroll
    for (int i = 0; i < ROW_CHUNKS / 4; ++i) {
        int c = cg * (ROW_CHUNKS / 4) + i;
        s += __ldcg(&g_part[c * N_NODES + j]);    // L2-resident partials
    }
    red[cg][jLocal] = s;
    __syncthreads();

    if (threadIdx.x < 256) {
        float t = red[0][jLocal] + red[1][jLocal] + red[2][jLocal] + red[3][jLocal];
        out[j] = gelu_erf(t + bias[j]);
    }
}

// ---------------------------------------------------------------------------
extern "C" void kernel_launch(void* const* d_in, const int* in_sizes, int n_in,
                              void* d_out, int out_size)
{
    const float* x     = (const float*)d_in[0];  // input_data [1,N]
    const int*   adj   = (const int*)d_in[1];    // adj [N,K] int32 (JAX x64 off)
    // d_in[2] = edge_weights (unused by reference)
    const float* W     = (const float*)d_in[3];  // [2N, N]
    const float* b     = (const float*)d_in[4];  // [N]
    const float* gamma = (const float*)d_in[5];  // [2N]
    const float* beta  = (const float*)d_in[6];  // [2N]
    const float* mean  = (const float*)d_in[7];  // [2N]
    const float* var   = (const float*)d_in[8];  // [2N]
    float*       out   = (float*)d_out;

    fused_kernel<<<GRID_TOTAL, THREADS_B>>>(x, adj, W, gamma, beta, mean, var);

    // K3 via PDL: overlap its launch/prologue with the fused kernel's tail.
    cudaLaunchConfig_t cfg = {};
    cfg.gridDim  = dim3(N_NODES / 256);
    cfg.blockDim = dim3(1024);
    cfg.dynamicSmemBytes = 0;
    cfg.stream = 0;
    cudaLaunchAttribute attrs[1];
    attrs[0].id = cudaLaunchAttributeProgrammaticStreamSerialization;
    attrs[0].val.programmaticStreamSerializationAllowed = 1;
    cfg.attrs = attrs;
    cfg.numAttrs = 1;
    cudaLaunchKernelEx(&cfg, reduce_gelu_kernel, b, out);
}

// round 17
// speedup vs baseline: 1.0256x; 1.0144x over previous
#include <cuda_runtime.h>
#include <math.h>

#define N_NODES   8192
#define K_NBR     64
#define TWO_N     (2 * N_NODES)
#define BN_EPS    1e-3f

// Fused kernel: 64 builders + 512 GEMV blocks = 576 blocks, all co-resident
// (148 SMs x ~4 blocks at 256 threads) -> spin is deadlock-free.
// Chunk c covers rows [128c,128c+128) u [N+128c, N+128c+128): each GEMV
// block streams its dependency-free lower half FIRST (~35us of W), so the
// builder flag is long set when the upper half starts -> zero wait.
#define N_BUILDERS     64
#define NODES_PER_B    (N_NODES / N_BUILDERS)   // 128
#define COL_TILES      8
#define ROW_CHUNKS     64
#define HALF_ROWS      128                       // rows per phase
#define THREADS_B      256
#define GRID_TOTAL     (N_BUILDERS + COL_TILES * ROW_CHUNKS)

// scratch (no allocation allowed). Zero-initialized at load; flags/counters
// self-reset every execution -> graph-replay safe.
__device__ float g_h[TWO_N];                     // only rows >= N used
__device__ float g_part[ROW_CHUNKS * N_NODES];
__device__ int   g_flag[N_BUILDERS];
__device__ int   g_cnt[N_BUILDERS];

__device__ __forceinline__ float gelu_erf(float z) {
    return 0.5f * z * (1.0f + erff(z * 0.70710678118654752440f));
}

// ---------------------------------------------------------------------------
__global__ __launch_bounds__(THREADS_B)
void fused_kernel(const float* __restrict__ x,
                  const int* __restrict__ adj,
                  const float* __restrict__ W,
                  const float* __restrict__ gamma,
                  const float* __restrict__ beta,
                  const float* __restrict__ mean,
                  const float* __restrict__ var)
{
    __shared__ float sh[2 * HALF_ROWS];
    const int tid = threadIdx.x;

    if (blockIdx.x < N_BUILDERS) {
        // ================= builder b: BN(x + ngh_sum) for nodes [128b,+128)
        const int b        = blockIdx.x;
        const int warpId   = tid >> 5;
        const int lane     = tid & 31;
        const int nodeBase = b * NODES_PER_B + warpId * 16;   // 16 nodes/warp
        const int2* adj2   = reinterpret_cast<const int2*>(adj);

        #pragma unroll
        for (int g = 0; g < 16; g += 8) {
            int2 a[8];
            #pragma unroll
            for (int i = 0; i < 8; ++i)
                a[i] = __ldg(&adj2[(nodeBase + g + i) * 32 + lane]);

            float s[8];
            #pragma unroll
            for (int i = 0; i < 8; ++i)
                s[i] = __ldg(&x[a[i].x]) + __ldg(&x[a[i].y]);

            #pragma unroll
            for (int off = 16; off > 0; off >>= 1) {
                #pragma unroll
                for (int i = 0; i < 8; ++i)
                    s[i] += __shfl_down_sync(0xffffffffu, s[i], off);
            }

            if (lane == 0) {
                #pragma unroll
                for (int i = 0; i < 8; ++i) {
                    const int node = nodeBase + g + i;
                    const int j    = N_NODES + node;
                    float agg = __ldg(&x[node]) + s[i];
                    float inv = rsqrtf(var[j] + BN_EPS);
                    g_h[j] = (agg - mean[j]) * inv * gamma[j] + beta[j];
                }
            }
        }

        __threadfence();
        __syncthreads();
        if (tid == 0)
            atomicExch(&g_flag[b], 1);   // release
        return;
    }

    // ================= GEMV block ==========================================
    const int gid     = blockIdx.x - N_BUILDERS;
    const int colTile = gid & (COL_TILES - 1);
    const int chunk   = gid >> 3;                 // 0..63
    const int colBase = colTile * (THREADS_B * 4) + tid * 4;
    const int rowA    = chunk * HALF_ROWS;        // lower-half base (< N)
    const int rowB    = N_NODES + rowA;           // upper-half base (>= N)

    // ---- phase A: dependency-free lower rows, stream starts immediately --
    if (tid < HALF_ROWS) {
        const int row = rowA + tid;
        float v   = x[row];
        float inv = rsqrtf(var[row] + BN_EPS);
        sh[tid] = (v - mean[row]) * inv * gamma[row] + beta[row];
    }
    __syncthreads();

    float4 acc = make_float4(0.f, 0.f, 0.f, 0.f);
    {
        const float4* wp = reinterpret_cast<const float4*>(
            W + (long long)rowA * N_NODES + colBase);
        const int strideV = N_NODES / 4;
        #pragma unroll 16
        for (int r = 0; r < HALF_ROWS; ++r) {
            float  hv = sh[r];
            float4 w  = __ldcs(wp);       // evict-first: W is read-once
            acc.x = fmaf(hv, w.x, acc.x);
            acc.y = fmaf(hv, w.y, acc.y);
            acc.z = fmaf(hv, w.z, acc.z);
            acc.w = fmaf(hv, w.w, acc.w);
            wp += strideV;
        }
    }

    // ---- phase B: upper rows; builder long done -> first poll passes -----
    if (tid == 0) {
        while (atomicAdd(&g_flag[chunk], 0) == 0) __nanosleep(64);
        __threadfence();   // acquire
    }
    __syncthreads();
    if (tid < HALF_ROWS)
        sh[HALF_ROWS + tid] = __ldcg(&g_h[rowB + tid]);
    __syncthreads();
    // self-resetting consumption (8 consumer blocks per flag)
    if (tid == 0) {
        if (atomicAdd(&g_cnt[chunk], 1) == COL_TILES - 1) {
            atomicExch(&g_cnt[chunk], 0);
            atomicExch(&g_flag[chunk], 0);
        }
    }

    {
        const float4* wp = reinterpret_cast<const float4*>(
            W + (long long)rowB * N_NODES + colBase);
        const int strideV = N_NODES / 4;
        #pragma unroll 16
        for (int r = 0; r < HALF_ROWS; ++r) {
            float  hv = sh[HALF_ROWS + r];
            float4 w  = __ldcs(wp);       // evict-first: W is read-once
            acc.x = fmaf(hv, w.x, acc.x);
            acc.y = fmaf(hv, w.y, acc.y);
            acc.z = fmaf(hv, w.z, acc.z);
            acc.w = fmaf(hv, w.w, acc.w);
            wp += strideV;
        }
    }

    *reinterpret_cast<float4*>(&g_part[chunk * N_NODES + colBase]) = acc;
}

// ---------------------------------------------------------------------------
// K3: two-level parallel reduce + bias + exact-erf gelu.
// Launched with PDL: blocks start while fused_kernel drains; the
// grid-dependency sync releases once all fused blocks complete. With W
// loaded via __ldcs, the 2MB of partials stay L2-resident -> fast reads.
// ---------------------------------------------------------------------------
__global__ __launch_bounds__(1024)
void reduce_gelu_kernel(const float* __restrict__ bias,
                        float* __restrict__ out)
{
    cudaGridDependencySynchronize();   // PDL: wait for fused_kernel completion

    __shared__ float red[4][256];

    const int jLocal = threadIdx.x & 255;
    const int cg     = threadIdx.x >> 8;          // 0..3
    const int j      = blockIdx.x * 256 + jLocal;

    float s = 0.f;
    #pragma unroll
    for (int i = 0; i < ROW_CHUNKS / 4; ++i) {
        int c = cg * (ROW_CHUNKS / 4) + i;
        s += __ldcg(&g_part[c * N_NODES + j]);    // L2-resident partials
    }
    red[cg][jLocal] = s;
    __syncthreads();

    if (threadIdx.x < 256) {
        float t = red[0][jLocal] + red[1][jLocal] + red[2][jLocal] + red[3][jLocal];
        out[j] = gelu_erf(t + bias[j]);
    }
}

// ---------------------------------------------------------------------------
extern "C" void kernel_launch(void* const* d_in, const int* in_sizes, int n_in,
                              void* d_out, int out_size)
{
    const float* x     = (const float*)d_in[0];  // input_data [1,N]
    const int*   adj   = (const int*)d_in[1];    // adj [N,K] int32 (JAX x64 off)
    // d_in[2] = edge_weights (unused by reference)
    const float* W     = (const float*)d_in[3];  // [2N, N]
    const float* b     = (const float*)d_in[4];  // [N]
    const float* gamma = (const float*)d_in[5];  // [2N]
    const float* beta  = (const float*)d_in[6];  // [2N]
    const float* mean  = (const float*)d_in[7];  // [2N]
    const float* var   = (const float*)d_in[8];  // [2N]
    float*       out   = (float*)d_out;

    fused_kernel<<<GRID_TOTAL, THREADS_B>>>(x, adj, W, gamma, beta, mean, var);

    // K3 via PDL: overlap its launch/prologue with the fused kernel's tail.
    cudaLaunchConfig_t cfg = {};
    cfg.gridDim  = dim3(N_NODES / 256);
    cfg.blockDim = dim3(1024);
    cfg.dynamicSmemBytes = 0;
    cfg.stream = 0;
    cudaLaunchAttribute attrs[1];
    attrs[0].id = cudaLaunchAttributeProgrammaticStreamSerialization;
    attrs[0].val.programmaticStreamSerializationAllowed = 1;
    cfg.attrs = attrs;
    cfg.numAttrs = 1;
    cudaLaunchKernelEx(&cfg, reduce_gelu_kernel, b, out);
}